// round 15
// baseline (speedup 1.0000x reference)
#include <cuda_runtime.h>
#include <cuda_bf16.h>
#include <mma.h>

using namespace nvcuda;

#define N_CONS 10000
#define N_COLS 10000
#define NN     20000
#define NE     200000
#define NE2    (NE + NN)        // edges + self loops = 220000
#define NEG_SLOPE 0.2f

// ---------------- scratch (static __device__ globals; no allocs) ------------
__device__ float g_emb0[(size_t)NN * 128];
__device__ float g_xp1 [(size_t)NN * 1024];
__device__ float g_emb1[(size_t)NN * 1024];
__device__ float g_xp2 [(size_t)NN * 128];
__device__ float g_emb2[(size_t)N_COLS * 128];   // compact: only column nodes
__device__ float g_asrc[(size_t)NN * 8];
__device__ float g_adst[(size_t)NN * 8];
__device__ float g_ws  [16 * 128];               // layer1 folded att vectors
__device__ int   g_deg[NN];
__device__ int   g_rowptr[NN + 1];
__device__ int   g_wpos[NN];
__device__ int   g_csrc[NE2];
__device__ int   g_part[64];
__device__ int   g_is64;

// ------------- initial embedding (+ CSR deg init + dtype detect) -----------
__global__ void k_embed(const float* __restrict__ cs, const float* __restrict__ co,
                        const float* __restrict__ nW, const float* __restrict__ nb,
                        const float* __restrict__ cW, const float* __restrict__ cb,
                        const void* __restrict__ ed)
{
    int idx = blockIdx.x * blockDim.x + threadIdx.x;
    if (idx == 0) {
        const int* p = (const int*)ed;
        int all0 = 1;
        for (int q = 0; q < 32; q++) all0 &= (p[2 * q + 1] == 0);
        g_is64 = all0;
    }
    if (idx < NN) g_deg[idx] = 1;   // self loop
    if (idx >= NN * 128) return;
    int n = idx >> 7, k = idx & 127;
    float s;
    if (n < N_CONS) {
        s = nb[k];
        const float* x = cs + (size_t)n * 4;
        const float* w = nW + (size_t)k * 8;
#pragma unroll
        for (int j = 0; j < 8; j++) s += x[j & 3] * w[j];
    } else {
        int m = n - N_CONS;
        s = cb[k];
        const float* x = co + (size_t)m * 8;
        const float* w = cW + (size_t)k * 16;
#pragma unroll
        for (int j = 0; j < 16; j++) s += x[j & 7] * w[j];
    }
    g_emb0[idx] = fmaxf(s, 0.f);
}

// -------- fold attention vectors through W1: ws_{src,dst}[h] = W1_h^T att[h]
__global__ void k_foldatt(const float* __restrict__ W1,
                          const float* __restrict__ as1, const float* __restrict__ ad1)
{
    int h = blockIdx.x, k = threadIdx.x;
    float ss = 0.f, sd = 0.f;
#pragma unroll 4
    for (int c = 0; c < 128; c++) {
        float w = W1[(size_t)(h * 128 + c) * 128 + k];
        ss += as1[h * 128 + c] * w;
        sd += ad1[h * 128 + c] * w;
    }
    g_ws[(h * 2 + 0) * 128 + k] = ss;
    g_ws[(h * 2 + 1) * 128 + k] = sd;
}

// -------- layer-1 attention logits from emb0: a[n,h] = emb0[n]·ws[h] -------
__global__ void k_attsmall(const float* __restrict__ emb0)
{
    __shared__ float sws[16 * 128];
    int tid = threadIdx.x;
    for (int i = tid; i < 16 * 128; i += 256) sws[i] = g_ws[i];
    __syncthreads();
    int lane = tid & 31, w = tid >> 5;
    int n = blockIdx.x * 8 + w;
    if (n >= NN) return;
    float4 v = *(const float4*)(emb0 + (size_t)n * 128 + lane * 4);
    float dots[16];
#pragma unroll
    for (int j = 0; j < 16; j++) {
        const float4 u = *(const float4*)&sws[j * 128 + lane * 4];
        dots[j] = v.x*u.x + v.y*u.y + v.z*u.z + v.w*u.w;
    }
#pragma unroll
    for (int o = 16; o; o >>= 1)
#pragma unroll
        for (int j = 0; j < 16; j++)
            dots[j] += __shfl_xor_sync(~0u, dots[j], o);
    if (lane < 8)       g_asrc[n * 8 + lane] = dots[lane * 2];
    else if (lane < 16) g_adst[n * 8 + (lane - 8)] = dots[(lane - 8) * 2 + 1];
}

// ---------------- bf16 3-MMA compensated GEMM with register prefetch -------
#define SST 40
__device__ __forceinline__ unsigned pk2(__nv_bfloat16 a, __nv_bfloat16 b)
{
    __nv_bfloat162 t; t.x = a; t.y = b;
    return *(unsigned*)&t;
}

template <bool RELU, bool BIAS, int BM>
__global__ __launch_bounds__(256, 2)
void k_gemm_tc(const float* __restrict__ A, const float* __restrict__ W,
               const float* __restrict__ bias, float* __restrict__ C,
               int M, int N, int K)
{
    constexpr int NA = BM / 64;
    constexpr int MI = BM / 32;
    __shared__ __align__(16) __nv_bfloat16 Ah[BM * SST];
    __shared__ __align__(16) __nv_bfloat16 Al[BM * SST];
    __shared__ __align__(16) __nv_bfloat16 Bh[128 * SST];
    __shared__ __align__(16) __nv_bfloat16 Bl[128 * SST];

    const int tid = threadIdx.x;
    const int wid = tid >> 5, lane = tid & 31;
    const int wm = wid >> 2, wn = wid & 3;
    const int m0 = blockIdx.y * BM, n0 = blockIdx.x * 128;

    int arow[NA], ac8[NA], brow[2], bc8[2];
#pragma unroll
    for (int l = 0; l < NA; l++) {
        int g = tid * NA + l;
        arow[l] = g >> 2; ac8[l] = (g & 3) * 8;
    }
#pragma unroll
    for (int l = 0; l < 2; l++) {
        int g = tid * 2 + l;
        brow[l] = g >> 2; bc8[l] = (g & 3) * 8;
    }

    float ax[NA][8], bx[2][8];

    auto loadTiles = [&](int k0) {
#pragma unroll
        for (int l = 0; l < NA; l++) {
            const float* ap = A + (size_t)(m0 + arow[l]) * K + k0 + ac8[l];
            if (m0 + arow[l] < M) {
                float4 u = *(const float4*)ap, v = *(const float4*)(ap + 4);
                ax[l][0]=u.x; ax[l][1]=u.y; ax[l][2]=u.z; ax[l][3]=u.w;
                ax[l][4]=v.x; ax[l][5]=v.y; ax[l][6]=v.z; ax[l][7]=v.w;
            } else {
#pragma unroll
                for (int q = 0; q < 8; q++) ax[l][q] = 0.f;
            }
        }
#pragma unroll
        for (int l = 0; l < 2; l++) {
            const float* wp = W + (size_t)(n0 + brow[l]) * K + k0 + bc8[l];
            float4 u = *(const float4*)wp, v = *(const float4*)(wp + 4);
            bx[l][0]=u.x; bx[l][1]=u.y; bx[l][2]=u.z; bx[l][3]=u.w;
            bx[l][4]=v.x; bx[l][5]=v.y; bx[l][6]=v.z; bx[l][7]=v.w;
        }
    };
    auto storeTiles = [&]() {
#pragma unroll
        for (int l = 0; l < NA; l++) {
            __nv_bfloat16 h[8], lo[8];
#pragma unroll
            for (int q = 0; q < 8; q++) {
                h[q]  = __float2bfloat16(ax[l][q]);
                lo[q] = __float2bfloat16(ax[l][q] - __bfloat162float(h[q]));
            }
            *(uint4*)&Ah[arow[l] * SST + ac8[l]] =
                make_uint4(pk2(h[0],h[1]), pk2(h[2],h[3]),
                           pk2(h[4],h[5]), pk2(h[6],h[7]));
            *(uint4*)&Al[arow[l] * SST + ac8[l]] =
                make_uint4(pk2(lo[0],lo[1]), pk2(lo[2],lo[3]),
                           pk2(lo[4],lo[5]), pk2(lo[6],lo[7]));
        }
#pragma unroll
        for (int l = 0; l < 2; l++) {
            __nv_bfloat16 h[8], lo[8];
#pragma unroll
            for (int q = 0; q < 8; q++) {
                h[q]  = __float2bfloat16(bx[l][q]);
                lo[q] = __float2bfloat16(bx[l][q] - __bfloat162float(h[q]));
            }
            *(uint4*)&Bh[brow[l] * SST + bc8[l]] =
                make_uint4(pk2(h[0],h[1]), pk2(h[2],h[3]),
                           pk2(h[4],h[5]), pk2(h[6],h[7]));
            *(uint4*)&Bl[brow[l] * SST + bc8[l]] =
                make_uint4(pk2(lo[0],lo[1]), pk2(lo[2],lo[3]),
                           pk2(lo[4],lo[5]), pk2(lo[6],lo[7]));
        }
    };

    wmma::fragment<wmma::accumulator, 16, 16, 16, float> acc[MI][2];
#pragma unroll
    for (int i = 0; i < MI; i++)
#pragma unroll
        for (int j = 0; j < 2; j++) wmma::fill_fragment(acc[i][j], 0.f);

    loadTiles(0);
    for (int k0 = 0; k0 < K; k0 += 32) {
        storeTiles();
        __syncthreads();
        if (k0 + 32 < K) loadTiles(k0 + 32);

#pragma unroll
        for (int kk = 0; kk < 32; kk += 16) {
            wmma::fragment<wmma::matrix_b, 16, 16, 16, __nv_bfloat16,
                           wmma::col_major> bh[2], bl[2];
#pragma unroll
            for (int j = 0; j < 2; j++) {
                int nb_ = wn * 32 + j * 16;
                wmma::load_matrix_sync(bh[j], &Bh[nb_ * SST + kk], SST);
                wmma::load_matrix_sync(bl[j], &Bl[nb_ * SST + kk], SST);
            }
#pragma unroll
            for (int i = 0; i < MI; i++) {
                int ma = wm * (BM / 2) + i * 16;
                wmma::fragment<wmma::matrix_a, 16, 16, 16, __nv_bfloat16,
                               wmma::row_major> ah, al;
                wmma::load_matrix_sync(ah, &Ah[ma * SST + kk], SST);
                wmma::load_matrix_sync(al, &Al[ma * SST + kk], SST);
#pragma unroll
                for (int j = 0; j < 2; j++) {
                    wmma::mma_sync(acc[i][j], ah, bh[j], acc[i][j]);
                    wmma::mma_sync(acc[i][j], ah, bl[j], acc[i][j]);
                    wmma::mma_sync(acc[i][j], al, bh[j], acc[i][j]);
                }
            }
        }
        __syncthreads();
    }

    float* sb = (float*)Bh + wid * 256;
#pragma unroll
    for (int i = 0; i < MI; i++) {
#pragma unroll
        for (int j = 0; j < 2; j++) {
            wmma::store_matrix_sync(sb, acc[i][j], 16, wmma::mem_row_major);
            __syncwarp();
#pragma unroll
            for (int e = 0; e < 8; e++) {
                int idx = e * 32 + lane;
                int r = idx >> 4, c = idx & 15;
                int m = m0 + wm * (BM / 2) + i * 16 + r;
                int n = n0 + wn * 32 + j * 16 + c;
                if (m < M) {
                    float v = sb[idx];
                    if (BIAS) v += bias[n];
                    if (RELU) v = fmaxf(v, 0.f);
                    C[(size_t)m * N + n] = v;
                }
            }
            __syncwarp();
        }
    }
}

// ---------------- attention logits per node (layer 2, H=1) -----------------
__global__ void k_att(const float* __restrict__ xp, const float* __restrict__ asv,
                      const float* __restrict__ adv, int H)
{
    int wid  = (blockIdx.x * blockDim.x + threadIdx.x) >> 5;
    int lane = threadIdx.x & 31;
    if (wid >= NN * H) return;
    int n = wid / H, h = wid % H;
    const float4* row = (const float4*)(xp  + ((size_t)n * H + h) * 128);
    const float4* as  = (const float4*)(asv + (size_t)h * 128);
    const float4* ad  = (const float4*)(adv + (size_t)h * 128);
    float4 v = row[lane], a = as[lane], b = ad[lane];
    float s = v.x*a.x + v.y*a.y + v.z*a.z + v.w*a.w;
    float d = v.x*b.x + v.y*b.y + v.z*b.z + v.w*b.w;
#pragma unroll
    for (int o = 16; o; o >>= 1) {
        s += __shfl_xor_sync(~0u, s, o);
        d += __shfl_xor_sync(~0u, d, o);
    }
    if (lane == 0) { g_asrc[n * H + h] = s; g_adst[n * H + h] = d; }
}

// ---------------- CSR build (by destination; includes self loops) ----------
__global__ void k_count(const void* ed)
{
    int e = blockIdx.x * blockDim.x + threadIdx.x;
    if (e >= NE) return;
    int d = g_is64 ? (int)((const long long*)ed)[NE + e]
                   : ((const int*)ed)[NE + e];
    atomicAdd(&g_deg[d], 1);
}
#define SCB 40
__global__ void k_scan1()
{
    int i = blockIdx.x * 512 + threadIdx.x;
    int lane = threadIdx.x & 31, w = threadIdx.x >> 5;
    int v = (i < NN) ? g_deg[i] : 0;
    int s = v;
#pragma unroll
    for (int o = 16; o; o >>= 1) s += __shfl_xor_sync(~0u, s, o);
    __shared__ int ws[16];
    if (lane == 0) ws[w] = s;
    __syncthreads();
    if (w == 0) {
        int t = (lane < 16) ? ws[lane] : 0;
#pragma unroll
        for (int o = 8; o; o >>= 1) t += __shfl_xor_sync(~0u, t, o);
        if (lane == 0) g_part[blockIdx.x] = t;
    }
}
__global__ void k_scan3()
{
    int i = blockIdx.x * 512 + threadIdx.x;
    int lane = threadIdx.x & 31, w = threadIdx.x >> 5;
    __shared__ int ws[16];
    __shared__ int poff;
    int v = (i < NN) ? g_deg[i] : 0;
    int incl = v;
#pragma unroll
    for (int o = 1; o < 32; o <<= 1) {
        int t = __shfl_up_sync(~0u, incl, o);
        if (lane >= o) incl += t;
    }
    if (lane == 31) ws[w] = incl;
    if (w == 1) {
        int a = (2 * lane < SCB)     ? g_part[2 * lane]     : 0;
        int b = (2 * lane + 1 < SCB) ? g_part[2 * lane + 1] : 0;
        int ps = a + b, inc2 = ps;
#pragma unroll
        for (int o = 1; o < 32; o <<= 1) {
            int t = __shfl_up_sync(~0u, inc2, o);
            if (lane >= o) inc2 += t;
        }
        int excl2 = inc2 - ps;
        if (2 * lane == blockIdx.x)     poff = excl2;
        if (2 * lane + 1 == blockIdx.x) poff = excl2 + a;
    }
    __syncthreads();
    if (w == 0 && lane < 16) {
        int t = ws[lane], s = t;
#pragma unroll
        for (int o = 1; o < 16; o <<= 1) {
            int u = __shfl_up_sync(0xffffu, s, o);
            if (lane >= o) s += u;
        }
        ws[lane] = s - t;
    }
    __syncthreads();
    int excl = poff + ws[w] + incl - v;
    if (i < NN) {
        g_rowptr[i] = excl;
        g_wpos[i]   = excl;
        if (i == NN - 1) g_rowptr[NN] = excl + v;
    }
}
__global__ void k_scatter(const void* ed)
{
    int e = blockIdx.x * blockDim.x + threadIdx.x;
    if (e >= NE2) return;
    int s, d;
    if (e < NE) {
        if (g_is64) { s = (int)((const long long*)ed)[e]; d = (int)((const long long*)ed)[NE + e]; }
        else        { s = ((const int*)ed)[e];            d = ((const int*)ed)[NE + e]; }
    } else {
        s = d = e - NE;
    }
    int p = atomicAdd(&g_wpos[d], 1);
    g_csrc[p] = s;
}

// ------- layer-1 fused softmax+agg: WARP PER DST, all 8 heads at once ------
__global__ void k_softagg8(const float* __restrict__ xp, const float* __restrict__ bias,
                           float* __restrict__ out)
{
    int wwid = (blockIdx.x * blockDim.x + threadIdx.x) >> 5;
    int lane = threadIdx.x & 31;
    if (wwid >= NN) return;
    int dst = wwid;
    int beg = g_rowptr[dst], end = g_rowptr[dst + 1];

    int h8 = lane & 7;
    float ad = g_adst[dst * 8 + h8];
    float m = -1e30f, s = 0.f;
    for (int i = beg + (lane >> 3); i < end; i += 4) {
        float e = g_asrc[g_csrc[i] * 8 + h8] + ad;
        e = e > 0.f ? e : NEG_SLOPE * e;
        float mn = fmaxf(m, e);
        s = s * __expf(m - mn) + __expf(e - mn);
        m = mn;
    }
#pragma unroll
    for (int o = 8; o <= 16; o <<= 1) {
        float mo = __shfl_xor_sync(~0u, m, o);
        float so = __shfl_xor_sync(~0u, s, o);
        float mn = fmaxf(m, mo);
        s = s * __expf(m - mn) + so * __expf(mo - mn);
        m = mn;
    }
    int hA = lane >> 2;
    float mA = __shfl_sync(~0u, m, hA);
    float sA = __shfl_sync(~0u, s, hA);
    float adA = g_adst[dst * 8 + hA];
    float invA = 1.f / (sA + 1e-16f);

    float4 acc[8];
#pragma unroll
    for (int q = 0; q < 8; q++) acc[q] = make_float4(0.f, 0.f, 0.f, 0.f);

    for (int i = beg; i < end; i++) {
        int   src = g_csrc[i];
        float e = g_asrc[src * 8 + hA] + adA;
        e = e > 0.f ? e : NEG_SLOPE * e;
        float a = __expf(e - mA) * invA;
        const float4* vp = (const float4*)(xp + (size_t)src * 1024 + hA * 128) + (lane & 3);
#pragma unroll
        for (int q = 0; q < 8; q++) {
            float4 v = vp[q * 4];
            acc[q].x += a * v.x; acc[q].y += a * v.y;
            acc[q].z += a * v.z; acc[q].w += a * v.w;
        }
    }
    const float4* bp = (const float4*)(bias + hA * 128) + (lane & 3);
    float4* op = (float4*)(out + (size_t)dst * 1024 + hA * 128) + (lane & 3);
#pragma unroll
    for (int q = 0; q < 8; q++) {
        float4 b = bp[q * 4];
        op[q * 4] = make_float4(fmaxf(acc[q].x + b.x, 0.f), fmaxf(acc[q].y + b.y, 0.f),
                                fmaxf(acc[q].z + b.z, 0.f), fmaxf(acc[q].w + b.w, 0.f));
    }
}

// ---------- layer-2 fused softmax+agg (warp per dst, H=1, compact) ---------
__global__ void k_softagg2(const float* __restrict__ xp, const float* __restrict__ bias,
                           float* __restrict__ out, int dst0, int ndst)
{
    int wid  = (blockIdx.x * blockDim.x + threadIdx.x) >> 5;
    int lane = threadIdx.x & 31;
    if (wid >= ndst) return;
    int dst = dst0 + wid;
    int beg = g_rowptr[dst], end = g_rowptr[dst + 1];
    float ad = g_adst[dst];

    float m = -1e30f, s = 0.f;
    for (int i = beg + lane; i < end; i += 32) {
        float e = g_asrc[g_csrc[i]] + ad;
        e = e > 0.f ? e : NEG_SLOPE * e;
        float mn = fmaxf(m, e);
        s = s * __expf(m - mn) + __expf(e - mn);
        m = mn;
    }
#pragma unroll
    for (int o = 16; o; o >>= 1) {
        float mo = __shfl_xor_sync(~0u, m, o);
        float so = __shfl_xor_sync(~0u, s, o);
        float mn = fmaxf(m, mo);
        s = s * __expf(m - mn) + so * __expf(mo - mn);
        m = mn;
    }
    float inv = 1.f / (s + 1e-16f);

    // unroll-2 aggregation: two independent gathers in flight
    float4 acc0 = make_float4(0.f, 0.f, 0.f, 0.f);
    float4 acc1 = make_float4(0.f, 0.f, 0.f, 0.f);
    int i = beg;
    for (; i + 1 < end; i += 2) {
        int s0 = g_csrc[i], s1 = g_csrc[i + 1];
        float e0 = g_asrc[s0] + ad, e1 = g_asrc[s1] + ad;
        e0 = e0 > 0.f ? e0 : NEG_SLOPE * e0;
        e1 = e1 > 0.f ? e1 : NEG_SLOPE * e1;
        float a0 = __expf(e0 - m) * inv, a1 = __expf(e1 - m) * inv;
        float4 v0 = *(const float4*)(xp + (size_t)s0 * 128 + lane * 4);
        float4 v1 = *(const float4*)(xp + (size_t)s1 * 128 + lane * 4);
        acc0.x += a0 * v0.x; acc0.y += a0 * v0.y; acc0.z += a0 * v0.z; acc0.w += a0 * v0.w;
        acc1.x += a1 * v1.x; acc1.y += a1 * v1.y; acc1.z += a1 * v1.z; acc1.w += a1 * v1.w;
    }
    if (i < end) {
        int s0 = g_csrc[i];
        float e0 = g_asrc[s0] + ad;
        e0 = e0 > 0.f ? e0 : NEG_SLOPE * e0;
        float a0 = __expf(e0 - m) * inv;
        float4 v0 = *(const float4*)(xp + (size_t)s0 * 128 + lane * 4);
        acc0.x += a0 * v0.x; acc0.y += a0 * v0.y; acc0.z += a0 * v0.z; acc0.w += a0 * v0.w;
    }
    acc0.x += acc1.x; acc0.y += acc1.y; acc0.z += acc1.z; acc0.w += acc1.w;

    const float* b = bias + lane * 4;
    float4 r = make_float4(fmaxf(acc0.x + b[0], 0.f), fmaxf(acc0.y + b[1], 0.f),
                           fmaxf(acc0.z + b[2], 0.f), fmaxf(acc0.w + b[3], 0.f));
    *(float4*)(out + (size_t)wid * 128 + lane * 4) = r;
}

// ---------------- launch ----------------------------------------------------
extern "C" void kernel_launch(void* const* d_in, const int* in_sizes, int n_in,
                              void* d_out, int out_size)
{
    const float* cs    = (const float*)d_in[0];
    const float* co    = (const float*)d_in[1];
    const float* nW    = (const float*)d_in[2];
    const float* nb    = (const float*)d_in[3];
    const float* cW    = (const float*)d_in[4];
    const float* cb    = (const float*)d_in[5];
    const float* W1    = (const float*)d_in[6];
    const float* as1   = (const float*)d_in[7];
    const float* ad1   = (const float*)d_in[8];
    const float* b1    = (const float*)d_in[9];
    const float* W2    = (const float*)d_in[10];
    const float* as2   = (const float*)d_in[11];
    const float* ad2   = (const float*)d_in[12];
    const float* b2    = (const float*)d_in[13];
    const float* oW    = (const float*)d_in[14];
    const float* ob    = (const float*)d_in[15];
    const void*  edges = (const void*)d_in[16];
    float* out = (float*)d_out;

    float *p_emb0, *p_xp1, *p_emb1, *p_xp2, *p_emb2;
    cudaGetSymbolAddress((void**)&p_emb0, g_emb0);
    cudaGetSymbolAddress((void**)&p_xp1,  g_xp1);
    cudaGetSymbolAddress((void**)&p_emb1, g_emb1);
    cudaGetSymbolAddress((void**)&p_xp2,  g_xp2);
    cudaGetSymbolAddress((void**)&p_emb2, g_emb2);

    // embeddings + deg init + dtype detect (fused)
    k_embed<<<(NN * 128 + 255) / 256, 256>>>(cs, co, nW, nb, cW, cb, edges);

    // ---- fork: CSR build + layer-1 att logits overlap GEMM1 ----
    cudaStream_t s2;
    cudaStreamCreateWithFlags(&s2, cudaStreamNonBlocking);
    cudaEvent_t eFork, eJoin;
    cudaEventCreateWithFlags(&eFork, cudaEventDisableTiming);
    cudaEventCreateWithFlags(&eJoin, cudaEventDisableTiming);

    cudaEventRecord(eFork, 0);
    cudaStreamWaitEvent(s2, eFork, 0);
    k_foldatt<<<8, 128, 0, s2>>>(W1, as1, ad1);
    k_count<<<(NE + 255) / 256, 256, 0, s2>>>(edges);
    k_scan1<<<SCB, 512, 0, s2>>>();
    k_scan3<<<SCB, 512, 0, s2>>>();
    k_scatter<<<(NE2 + 255) / 256, 256, 0, s2>>>(edges);
    k_attsmall<<<(NN + 7) / 8, 256, 0, s2>>>(p_emb0);
    cudaEventRecord(eJoin, s2);

    // main stream: GEMM1
    k_gemm_tc<false, false, 128><<<dim3(8, (NN + 127) / 128), 256>>>(
        p_emb0, W1, nullptr, p_xp1, NN, 1024, 128);

    // join CSR + att logits before softagg
    cudaStreamWaitEvent(0, eJoin, 0);

    // layer-1 aggregation: warp per dst, all 8 heads
    k_softagg8<<<(NN + 7) / 8, 256>>>(p_xp1, b1, p_emb1);

    // ----- GAT layer 2 (H=1, C=128): BM=64, 2 CTAs/SM -----
    k_gemm_tc<false, false, 64><<<dim3(1, (NN + 63) / 64), 256>>>(
        p_emb1, W2, nullptr, p_xp2, NN, 128, 1024);
    k_att<<<(NN * 1 + 7) / 8, 256>>>(p_xp2, as2, ad2, 1);
    k_softagg2<<<(N_COLS + 7) / 8, 256>>>(p_xp2, b2, p_emb2, N_CONS, N_COLS);

    // ----- logits = emb2_cols @ out_W^T + out_b (BM=64 wave balance) -----
    k_gemm_tc<false, true, 64><<<dim3(1, (N_COLS + 63) / 64), 256>>>(
        p_emb2, oW, ob, out, N_COLS, 128, 128);

    cudaEventDestroy(eFork);
    cudaEventDestroy(eJoin);
    cudaStreamDestroy(s2);
}

// round 16
// speedup vs baseline: 1.5175x; 1.5175x over previous
#include <cuda_runtime.h>
#include <cuda_bf16.h>
#include <mma.h>

using namespace nvcuda;

#define N_CONS 10000
#define N_COLS 10000
#define NN     20000
#define NE     200000
#define NE2    (NE + NN)        // edges + self loops = 220000
#define NEG_SLOPE 0.2f

// ---------------- scratch (static __device__ globals; no allocs) ------------
__device__ float g_emb0[(size_t)NN * 128];
__device__ float g_xp1 [(size_t)NN * 1024];
__device__ float g_emb1[(size_t)NN * 1024];
__device__ float g_xp2 [(size_t)NN * 128];
__device__ float g_emb2[(size_t)N_COLS * 128];   // compact: only column nodes
__device__ float g_asrc[(size_t)NN * 8];
__device__ float g_adst[(size_t)NN * 8];
__device__ float g_ws  [16 * 128];               // layer1 folded att vectors
__device__ int   g_deg[NN];
__device__ int   g_rowptr[NN + 1];
__device__ int   g_wpos[NN];
__device__ int   g_csrc[NE2];
__device__ int   g_part[64];
__device__ int   g_is64;

// ------------- initial embedding (+ CSR deg init + dtype detect) -----------
__global__ void k_embed(const float* __restrict__ cs, const float* __restrict__ co,
                        const float* __restrict__ nW, const float* __restrict__ nb,
                        const float* __restrict__ cW, const float* __restrict__ cb,
                        const void* __restrict__ ed)
{
    int idx = blockIdx.x * blockDim.x + threadIdx.x;
    if (idx == 0) {
        const int* p = (const int*)ed;
        int all0 = 1;
        for (int q = 0; q < 32; q++) all0 &= (p[2 * q + 1] == 0);
        g_is64 = all0;
    }
    if (idx < NN) g_deg[idx] = 1;   // self loop
    if (idx >= NN * 128) return;
    int n = idx >> 7, k = idx & 127;
    float s;
    if (n < N_CONS) {
        s = nb[k];
        const float* x = cs + (size_t)n * 4;
        const float* w = nW + (size_t)k * 8;
#pragma unroll
        for (int j = 0; j < 8; j++) s += x[j & 3] * w[j];
    } else {
        int m = n - N_CONS;
        s = cb[k];
        const float* x = co + (size_t)m * 8;
        const float* w = cW + (size_t)k * 16;
#pragma unroll
        for (int j = 0; j < 16; j++) s += x[j & 7] * w[j];
    }
    g_emb0[idx] = fmaxf(s, 0.f);
}

// -------- fold attention vectors through W1: ws_{src,dst}[h] = W1_h^T att[h]
__global__ void k_foldatt(const float* __restrict__ W1,
                          const float* __restrict__ as1, const float* __restrict__ ad1)
{
    int h = blockIdx.x, k = threadIdx.x;
    float ss = 0.f, sd = 0.f;
#pragma unroll 4
    for (int c = 0; c < 128; c++) {
        float w = W1[(size_t)(h * 128 + c) * 128 + k];
        ss += as1[h * 128 + c] * w;
        sd += ad1[h * 128 + c] * w;
    }
    g_ws[(h * 2 + 0) * 128 + k] = ss;
    g_ws[(h * 2 + 1) * 128 + k] = sd;
}

// -------- layer-1 attention logits from emb0: a[n,h] = emb0[n]·ws[h] -------
__global__ void k_attsmall(const float* __restrict__ emb0)
{
    __shared__ float sws[16 * 128];
    int tid = threadIdx.x;
    for (int i = tid; i < 16 * 128; i += 256) sws[i] = g_ws[i];
    __syncthreads();
    int lane = tid & 31, w = tid >> 5;
    int n = blockIdx.x * 8 + w;
    if (n >= NN) return;
    float4 v = *(const float4*)(emb0 + (size_t)n * 128 + lane * 4);
    float dots[16];
#pragma unroll
    for (int j = 0; j < 16; j++) {
        const float4 u = *(const float4*)&sws[j * 128 + lane * 4];
        dots[j] = v.x*u.x + v.y*u.y + v.z*u.z + v.w*u.w;
    }
#pragma unroll
    for (int o = 16; o; o >>= 1)
#pragma unroll
        for (int j = 0; j < 16; j++)
            dots[j] += __shfl_xor_sync(~0u, dots[j], o);
    if (lane < 8)       g_asrc[n * 8 + lane] = dots[lane * 2];
    else if (lane < 16) g_adst[n * 8 + (lane - 8)] = dots[(lane - 8) * 2 + 1];
}

// ---------------- bf16 3-MMA compensated GEMM with register prefetch -------
#define SST 40
__device__ __forceinline__ unsigned pk2(__nv_bfloat16 a, __nv_bfloat16 b)
{
    __nv_bfloat162 t; t.x = a; t.y = b;
    return *(unsigned*)&t;
}

template <bool RELU, bool BIAS, int BM>
__global__ __launch_bounds__(256, 2)
void k_gemm_tc(const float* __restrict__ A, const float* __restrict__ W,
               const float* __restrict__ bias, float* __restrict__ C,
               int M, int N, int K)
{
    constexpr int NA = BM / 64;
    constexpr int MI = BM / 32;
    __shared__ __align__(16) __nv_bfloat16 Ah[BM * SST];
    __shared__ __align__(16) __nv_bfloat16 Al[BM * SST];
    __shared__ __align__(16) __nv_bfloat16 Bh[128 * SST];
    __shared__ __align__(16) __nv_bfloat16 Bl[128 * SST];

    const int tid = threadIdx.x;
    const int wid = tid >> 5, lane = tid & 31;
    const int wm = wid >> 2, wn = wid & 3;
    const int m0 = blockIdx.y * BM, n0 = blockIdx.x * 128;

    int arow[NA], ac8[NA], brow[2], bc8[2];
#pragma unroll
    for (int l = 0; l < NA; l++) {
        int g = tid * NA + l;
        arow[l] = g >> 2; ac8[l] = (g & 3) * 8;
    }
#pragma unroll
    for (int l = 0; l < 2; l++) {
        int g = tid * 2 + l;
        brow[l] = g >> 2; bc8[l] = (g & 3) * 8;
    }

    float ax[NA][8], bx[2][8];

    auto loadTiles = [&](int k0) {
#pragma unroll
        for (int l = 0; l < NA; l++) {
            const float* ap = A + (size_t)(m0 + arow[l]) * K + k0 + ac8[l];
            if (m0 + arow[l] < M) {
                float4 u = *(const float4*)ap, v = *(const float4*)(ap + 4);
                ax[l][0]=u.x; ax[l][1]=u.y; ax[l][2]=u.z; ax[l][3]=u.w;
                ax[l][4]=v.x; ax[l][5]=v.y; ax[l][6]=v.z; ax[l][7]=v.w;
            } else {
#pragma unroll
                for (int q = 0; q < 8; q++) ax[l][q] = 0.f;
            }
        }
#pragma unroll
        for (int l = 0; l < 2; l++) {
            const float* wp = W + (size_t)(n0 + brow[l]) * K + k0 + bc8[l];
            float4 u = *(const float4*)wp, v = *(const float4*)(wp + 4);
            bx[l][0]=u.x; bx[l][1]=u.y; bx[l][2]=u.z; bx[l][3]=u.w;
            bx[l][4]=v.x; bx[l][5]=v.y; bx[l][6]=v.z; bx[l][7]=v.w;
        }
    };
    auto storeTiles = [&]() {
#pragma unroll
        for (int l = 0; l < NA; l++) {
            __nv_bfloat16 h[8], lo[8];
#pragma unroll
            for (int q = 0; q < 8; q++) {
                h[q]  = __float2bfloat16(ax[l][q]);
                lo[q] = __float2bfloat16(ax[l][q] - __bfloat162float(h[q]));
            }
            *(uint4*)&Ah[arow[l] * SST + ac8[l]] =
                make_uint4(pk2(h[0],h[1]), pk2(h[2],h[3]),
                           pk2(h[4],h[5]), pk2(h[6],h[7]));
            *(uint4*)&Al[arow[l] * SST + ac8[l]] =
                make_uint4(pk2(lo[0],lo[1]), pk2(lo[2],lo[3]),
                           pk2(lo[4],lo[5]), pk2(lo[6],lo[7]));
        }
#pragma unroll
        for (int l = 0; l < 2; l++) {
            __nv_bfloat16 h[8], lo[8];
#pragma unroll
            for (int q = 0; q < 8; q++) {
                h[q]  = __float2bfloat16(bx[l][q]);
                lo[q] = __float2bfloat16(bx[l][q] - __bfloat162float(h[q]));
            }
            *(uint4*)&Bh[brow[l] * SST + bc8[l]] =
                make_uint4(pk2(h[0],h[1]), pk2(h[2],h[3]),
                           pk2(h[4],h[5]), pk2(h[6],h[7]));
            *(uint4*)&Bl[brow[l] * SST + bc8[l]] =
                make_uint4(pk2(lo[0],lo[1]), pk2(lo[2],lo[3]),
                           pk2(lo[4],lo[5]), pk2(lo[6],lo[7]));
        }
    };

    wmma::fragment<wmma::accumulator, 16, 16, 16, float> acc[MI][2];
#pragma unroll
    for (int i = 0; i < MI; i++)
#pragma unroll
        for (int j = 0; j < 2; j++) wmma::fill_fragment(acc[i][j], 0.f);

    loadTiles(0);
    for (int k0 = 0; k0 < K; k0 += 32) {
        storeTiles();
        __syncthreads();
        if (k0 + 32 < K) loadTiles(k0 + 32);

#pragma unroll
        for (int kk = 0; kk < 32; kk += 16) {
            wmma::fragment<wmma::matrix_b, 16, 16, 16, __nv_bfloat16,
                           wmma::col_major> bh[2], bl[2];
#pragma unroll
            for (int j = 0; j < 2; j++) {
                int nb_ = wn * 32 + j * 16;
                wmma::load_matrix_sync(bh[j], &Bh[nb_ * SST + kk], SST);
                wmma::load_matrix_sync(bl[j], &Bl[nb_ * SST + kk], SST);
            }
#pragma unroll
            for (int i = 0; i < MI; i++) {
                int ma = wm * (BM / 2) + i * 16;
                wmma::fragment<wmma::matrix_a, 16, 16, 16, __nv_bfloat16,
                               wmma::row_major> ah, al;
                wmma::load_matrix_sync(ah, &Ah[ma * SST + kk], SST);
                wmma::load_matrix_sync(al, &Al[ma * SST + kk], SST);
#pragma unroll
                for (int j = 0; j < 2; j++) {
                    wmma::mma_sync(acc[i][j], ah, bh[j], acc[i][j]);
                    wmma::mma_sync(acc[i][j], ah, bl[j], acc[i][j]);
                    wmma::mma_sync(acc[i][j], al, bh[j], acc[i][j]);
                }
            }
        }
        __syncthreads();
    }

    float* sb = (float*)Bh + wid * 256;
#pragma unroll
    for (int i = 0; i < MI; i++) {
#pragma unroll
        for (int j = 0; j < 2; j++) {
            wmma::store_matrix_sync(sb, acc[i][j], 16, wmma::mem_row_major);
            __syncwarp();
#pragma unroll
            for (int e = 0; e < 8; e++) {
                int idx = e * 32 + lane;
                int r = idx >> 4, c = idx & 15;
                int m = m0 + wm * (BM / 2) + i * 16 + r;
                int n = n0 + wn * 32 + j * 16 + c;
                if (m < M) {
                    float v = sb[idx];
                    if (BIAS) v += bias[n];
                    if (RELU) v = fmaxf(v, 0.f);
                    C[(size_t)m * N + n] = v;
                }
            }
            __syncwarp();
        }
    }
}

// ---------------- attention logits per node (layer 2, H=1) -----------------
__global__ void k_att(const float* __restrict__ xp, const float* __restrict__ asv,
                      const float* __restrict__ adv, int H)
{
    int wid  = (blockIdx.x * blockDim.x + threadIdx.x) >> 5;
    int lane = threadIdx.x & 31;
    if (wid >= NN * H) return;
    int n = wid / H, h = wid % H;
    const float4* row = (const float4*)(xp  + ((size_t)n * H + h) * 128);
    const float4* as  = (const float4*)(asv + (size_t)h * 128);
    const float4* ad  = (const float4*)(adv + (size_t)h * 128);
    float4 v = row[lane], a = as[lane], b = ad[lane];
    float s = v.x*a.x + v.y*a.y + v.z*a.z + v.w*a.w;
    float d = v.x*b.x + v.y*b.y + v.z*b.z + v.w*b.w;
#pragma unroll
    for (int o = 16; o; o >>= 1) {
        s += __shfl_xor_sync(~0u, s, o);
        d += __shfl_xor_sync(~0u, d, o);
    }
    if (lane == 0) { g_asrc[n * H + h] = s; g_adst[n * H + h] = d; }
}

// ---------------- CSR build (by destination; includes self loops) ----------
__global__ void k_count(const void* ed)
{
    int e = blockIdx.x * blockDim.x + threadIdx.x;
    if (e >= NE) return;
    int d = g_is64 ? (int)((const long long*)ed)[NE + e]
                   : ((const int*)ed)[NE + e];
    atomicAdd(&g_deg[d], 1);
}
#define SCB 40
__global__ void k_scan1()
{
    int i = blockIdx.x * 512 + threadIdx.x;
    int lane = threadIdx.x & 31, w = threadIdx.x >> 5;
    int v = (i < NN) ? g_deg[i] : 0;
    int s = v;
#pragma unroll
    for (int o = 16; o; o >>= 1) s += __shfl_xor_sync(~0u, s, o);
    __shared__ int ws[16];
    if (lane == 0) ws[w] = s;
    __syncthreads();
    if (w == 0) {
        int t = (lane < 16) ? ws[lane] : 0;
#pragma unroll
        for (int o = 8; o; o >>= 1) t += __shfl_xor_sync(~0u, t, o);
        if (lane == 0) g_part[blockIdx.x] = t;
    }
}
__global__ void k_scan3()
{
    int i = blockIdx.x * 512 + threadIdx.x;
    int lane = threadIdx.x & 31, w = threadIdx.x >> 5;
    __shared__ int ws[16];
    __shared__ int poff;
    int v = (i < NN) ? g_deg[i] : 0;
    int incl = v;
#pragma unroll
    for (int o = 1; o < 32; o <<= 1) {
        int t = __shfl_up_sync(~0u, incl, o);
        if (lane >= o) incl += t;
    }
    if (lane == 31) ws[w] = incl;
    if (w == 1) {
        int a = (2 * lane < SCB)     ? g_part[2 * lane]     : 0;
        int b = (2 * lane + 1 < SCB) ? g_part[2 * lane + 1] : 0;
        int ps = a + b, inc2 = ps;
#pragma unroll
        for (int o = 1; o < 32; o <<= 1) {
            int t = __shfl_up_sync(~0u, inc2, o);
            if (lane >= o) inc2 += t;
        }
        int excl2 = inc2 - ps;
        if (2 * lane == blockIdx.x)     poff = excl2;
        if (2 * lane + 1 == blockIdx.x) poff = excl2 + a;
    }
    __syncthreads();
    if (w == 0 && lane < 16) {
        int t = ws[lane], s = t;
#pragma unroll
        for (int o = 1; o < 16; o <<= 1) {
            int u = __shfl_up_sync(0xffffu, s, o);
            if (lane >= o) s += u;
        }
        ws[lane] = s - t;
    }
    __syncthreads();
    int excl = poff + ws[w] + incl - v;
    if (i < NN) {
        g_rowptr[i] = excl;
        g_wpos[i]   = excl;
        if (i == NN - 1) g_rowptr[NN] = excl + v;
    }
}
__global__ void k_scatter(const void* ed)
{
    int e = blockIdx.x * blockDim.x + threadIdx.x;
    if (e >= NE2) return;
    int s, d;
    if (e < NE) {
        if (g_is64) { s = (int)((const long long*)ed)[e]; d = (int)((const long long*)ed)[NE + e]; }
        else        { s = ((const int*)ed)[e];            d = ((const int*)ed)[NE + e]; }
    } else {
        s = d = e - NE;
    }
    int p = atomicAdd(&g_wpos[d], 1);
    g_csrc[p] = s;
}

// ------- layer-1 fused softmax+agg: WARP PER DST, all 8 heads at once ------
__global__ void k_softagg8(const float* __restrict__ xp, const float* __restrict__ bias,
                           float* __restrict__ out)
{
    int wwid = (blockIdx.x * blockDim.x + threadIdx.x) >> 5;
    int lane = threadIdx.x & 31;
    if (wwid >= NN) return;
    int dst = wwid;
    int beg = g_rowptr[dst], end = g_rowptr[dst + 1];

    int h8 = lane & 7;
    float ad = g_adst[dst * 8 + h8];
    float m = -1e30f, s = 0.f;
    for (int i = beg + (lane >> 3); i < end; i += 4) {
        float e = g_asrc[g_csrc[i] * 8 + h8] + ad;
        e = e > 0.f ? e : NEG_SLOPE * e;
        float mn = fmaxf(m, e);
        s = s * __expf(m - mn) + __expf(e - mn);
        m = mn;
    }
#pragma unroll
    for (int o = 8; o <= 16; o <<= 1) {
        float mo = __shfl_xor_sync(~0u, m, o);
        float so = __shfl_xor_sync(~0u, s, o);
        float mn = fmaxf(m, mo);
        s = s * __expf(m - mn) + so * __expf(mo - mn);
        m = mn;
    }
    int hA = lane >> 2;
    float mA = __shfl_sync(~0u, m, hA);
    float sA = __shfl_sync(~0u, s, hA);
    float adA = g_adst[dst * 8 + hA];
    float invA = 1.f / (sA + 1e-16f);

    float4 acc[8];
#pragma unroll
    for (int q = 0; q < 8; q++) acc[q] = make_float4(0.f, 0.f, 0.f, 0.f);

    for (int i = beg; i < end; i++) {
        int   src = g_csrc[i];
        float e = g_asrc[src * 8 + hA] + adA;
        e = e > 0.f ? e : NEG_SLOPE * e;
        float a = __expf(e - mA) * invA;
        const float4* vp = (const float4*)(xp + (size_t)src * 1024 + hA * 128) + (lane & 3);
#pragma unroll
        for (int q = 0; q < 8; q++) {
            float4 v = vp[q * 4];
            acc[q].x += a * v.x; acc[q].y += a * v.y;
            acc[q].z += a * v.z; acc[q].w += a * v.w;
        }
    }
    const float4* bp = (const float4*)(bias + hA * 128) + (lane & 3);
    float4* op = (float4*)(out + (size_t)dst * 1024 + hA * 128) + (lane & 3);
#pragma unroll
    for (int q = 0; q < 8; q++) {
        float4 b = bp[q * 4];
        op[q * 4] = make_float4(fmaxf(acc[q].x + b.x, 0.f), fmaxf(acc[q].y + b.y, 0.f),
                                fmaxf(acc[q].z + b.z, 0.f), fmaxf(acc[q].w + b.w, 0.f));
    }
}

// ---------- layer-2 fused softmax+agg (warp per dst, H=1, compact) ---------
__global__ void k_softagg2(const float* __restrict__ xp, const float* __restrict__ bias,
                           float* __restrict__ out, int dst0, int ndst)
{
    int wid  = (blockIdx.x * blockDim.x + threadIdx.x) >> 5;
    int lane = threadIdx.x & 31;
    if (wid >= ndst) return;
    int dst = dst0 + wid;
    int beg = g_rowptr[dst], end = g_rowptr[dst + 1];
    float ad = g_adst[dst];

    float m = -1e30f, s = 0.f;
    for (int i = beg + lane; i < end; i += 32) {
        float e = g_asrc[g_csrc[i]] + ad;
        e = e > 0.f ? e : NEG_SLOPE * e;
        float mn = fmaxf(m, e);
        s = s * __expf(m - mn) + __expf(e - mn);
        m = mn;
    }
#pragma unroll
    for (int o = 16; o; o >>= 1) {
        float mo = __shfl_xor_sync(~0u, m, o);
        float so = __shfl_xor_sync(~0u, s, o);
        float mn = fmaxf(m, mo);
        s = s * __expf(m - mn) + so * __expf(mo - mn);
        m = mn;
    }
    float inv = 1.f / (s + 1e-16f);

    // unroll-2 aggregation: two independent gathers in flight
    float4 acc0 = make_float4(0.f, 0.f, 0.f, 0.f);
    float4 acc1 = make_float4(0.f, 0.f, 0.f, 0.f);
    int i = beg;
    for (; i + 1 < end; i += 2) {
        int s0 = g_csrc[i], s1 = g_csrc[i + 1];
        float e0 = g_asrc[s0] + ad, e1 = g_asrc[s1] + ad;
        e0 = e0 > 0.f ? e0 : NEG_SLOPE * e0;
        e1 = e1 > 0.f ? e1 : NEG_SLOPE * e1;
        float a0 = __expf(e0 - m) * inv, a1 = __expf(e1 - m) * inv;
        float4 v0 = *(const float4*)(xp + (size_t)s0 * 128 + lane * 4);
        float4 v1 = *(const float4*)(xp + (size_t)s1 * 128 + lane * 4);
        acc0.x += a0 * v0.x; acc0.y += a0 * v0.y; acc0.z += a0 * v0.z; acc0.w += a0 * v0.w;
        acc1.x += a1 * v1.x; acc1.y += a1 * v1.y; acc1.z += a1 * v1.z; acc1.w += a1 * v1.w;
    }
    if (i < end) {
        int s0 = g_csrc[i];
        float e0 = g_asrc[s0] + ad;
        e0 = e0 > 0.f ? e0 : NEG_SLOPE * e0;
        float a0 = __expf(e0 - m) * inv;
        float4 v0 = *(const float4*)(xp + (size_t)s0 * 128 + lane * 4);
        acc0.x += a0 * v0.x; acc0.y += a0 * v0.y; acc0.z += a0 * v0.z; acc0.w += a0 * v0.w;
    }
    acc0.x += acc1.x; acc0.y += acc1.y; acc0.z += acc1.z; acc0.w += acc1.w;

    const float* b = bias + lane * 4;
    float4 r = make_float4(fmaxf(acc0.x + b[0], 0.f), fmaxf(acc0.y + b[1], 0.f),
                           fmaxf(acc0.z + b[2], 0.f), fmaxf(acc0.w + b[3], 0.f));
    *(float4*)(out + (size_t)wid * 128 + lane * 4) = r;
}

// ---------------- launch ----------------------------------------------------
extern "C" void kernel_launch(void* const* d_in, const int* in_sizes, int n_in,
                              void* d_out, int out_size)
{
    const float* cs    = (const float*)d_in[0];
    const float* co    = (const float*)d_in[1];
    const float* nW    = (const float*)d_in[2];
    const float* nb    = (const float*)d_in[3];
    const float* cW    = (const float*)d_in[4];
    const float* cb    = (const float*)d_in[5];
    const float* W1    = (const float*)d_in[6];
    const float* as1   = (const float*)d_in[7];
    const float* ad1   = (const float*)d_in[8];
    const float* b1    = (const float*)d_in[9];
    const float* W2    = (const float*)d_in[10];
    const float* as2   = (const float*)d_in[11];
    const float* ad2   = (const float*)d_in[12];
    const float* b2    = (const float*)d_in[13];
    const float* oW    = (const float*)d_in[14];
    const float* ob    = (const float*)d_in[15];
    const void*  edges = (const void*)d_in[16];
    float* out = (float*)d_out;

    float *p_emb0, *p_xp1, *p_emb1, *p_xp2, *p_emb2;
    cudaGetSymbolAddress((void**)&p_emb0, g_emb0);
    cudaGetSymbolAddress((void**)&p_xp1,  g_xp1);
    cudaGetSymbolAddress((void**)&p_emb1, g_emb1);
    cudaGetSymbolAddress((void**)&p_xp2,  g_xp2);
    cudaGetSymbolAddress((void**)&p_emb2, g_emb2);

    // embeddings + deg init + dtype detect (fused)
    k_embed<<<(NN * 128 + 255) / 256, 256>>>(cs, co, nW, nb, cW, cb, edges);

    // ---- fork: CSR build + layer-1 att logits overlap GEMM1 ----
    cudaStream_t s2;
    cudaStreamCreateWithFlags(&s2, cudaStreamNonBlocking);
    cudaEvent_t eFork, eJoin;
    cudaEventCreateWithFlags(&eFork, cudaEventDisableTiming);
    cudaEventCreateWithFlags(&eJoin, cudaEventDisableTiming);

    cudaEventRecord(eFork, 0);
    cudaStreamWaitEvent(s2, eFork, 0);
    k_foldatt<<<8, 128, 0, s2>>>(W1, as1, ad1);
    k_count<<<(NE + 255) / 256, 256, 0, s2>>>(edges);
    k_scan1<<<SCB, 512, 0, s2>>>();
    k_scan3<<<SCB, 512, 0, s2>>>();
    k_scatter<<<(NE2 + 255) / 256, 256, 0, s2>>>(edges);
    k_attsmall<<<(NN + 7) / 8, 256, 0, s2>>>(p_emb0);
    cudaEventRecord(eJoin, s2);

    // main stream: GEMM1
    k_gemm_tc<false, false, 128><<<dim3(8, (NN + 127) / 128), 256>>>(
        p_emb0, W1, nullptr, p_xp1, NN, 1024, 128);

    // join CSR + att logits before softagg
    cudaStreamWaitEvent(0, eJoin, 0);

    // layer-1 aggregation: warp per dst, all 8 heads
    k_softagg8<<<(NN + 7) / 8, 256>>>(p_xp1, b1, p_emb1);

    // ----- GAT layer 2 (H=1, C=128): BM=64, 2 CTAs/SM -----
    k_gemm_tc<false, false, 64><<<dim3(1, (NN + 63) / 64), 256>>>(
        p_emb1, W2, nullptr, p_xp2, NN, 128, 1024);
    k_att<<<(NN * 1 + 7) / 8, 256>>>(p_xp2, as2, ad2, 1);
    k_softagg2<<<(N_COLS + 7) / 8, 256>>>(p_xp2, b2, p_emb2, N_CONS, N_COLS);

    // ----- logits = emb2_cols @ out_W^T + out_b (BM=64 wave balance) -----
    k_gemm_tc<false, true, 64><<<dim3(1, (N_COLS + 63) / 64), 256>>>(
        p_emb2, oW, ob, out, N_COLS, 128, 128);

    cudaEventDestroy(eFork);
    cudaEventDestroy(eJoin);
    cudaStreamDestroy(s2);
}